// round 13
// baseline (speedup 1.0000x reference)
#include <cuda_runtime.h>
#include <cuda_bf16.h>
#include <cstdint>

#define N_NODES 100000
#define N_EDGES 600000
#define N_FEAT  128
#define TILE_M  64
#define NTILES  ((N_NODES + TILE_M - 1) / TILE_M)   // 1563

// Scratch (device globals). 16B alignment load-bearing for red.v4/int4 loads.
__device__ __align__(16) float g_deg[N_NODES];
__device__ __align__(16) float g_aggx[(size_t)N_NODES * N_FEAT];
__device__ __align__(16) int g_src[N_EDGES];
__device__ __align__(16) int g_dst[N_EDGES];
__device__ unsigned int g_or;   // dtype detection (0 => int64 layout)
// W fragments, hi/lo interleaved: uint4 = {bh.x, bh.y, bl.x, bl.y}
// index = (nb*8 + kstep)*32 + g*4 + t  -> warp load = 512 B contiguous.
__device__ __align__(16) uint4 g_whl[128 * 8 * 4];

// ---- prep: deg init + W split + dtype detect (one launch) ----
#define DEG_BLKS  ((N_NODES + 255) / 256)         // 391
#define WSP_BLKS  ((128 * 128 + 255) / 256)       // 64

__global__ void k_prep(const float* __restrict__ W,
                       const unsigned int* __restrict__ ew) {
    int bid = blockIdx.x, tid = threadIdx.x;
    if (bid < DEG_BLKS) {
        int i = bid * 256 + tid;
        if (i < N_NODES) g_deg[i] = 1.0f;          // self-loop pre-counted
        if (bid == 0) {
            __shared__ unsigned int s_or;
            if (tid == 0) s_or = 0u;
            __syncthreads();
            unsigned int v = 0u;
#pragma unroll
            for (int k = 0; k < 16; k++) {
                int e = (tid * 16 + k) * 146;      // <= 597,870 < N_EDGES
                v |= ew[2 * e + 1];
            }
#pragma unroll
            for (int s = 16; s > 0; s >>= 1)
                v |= __shfl_xor_sync(0xffffffffu, v, s);
            if ((tid & 31) == 0 && v) atomicOr(&s_or, v);
            __syncthreads();
            if (tid == 0) g_or = s_or;
        }
    } else {
        int i = (bid - DEG_BLKS) * 256 + tid;      // W split
        if (i < 128 * 128) {
            int k = i >> 7, n = i & 127;
            float v = W[i];
            __nv_bfloat16 h = __float2bfloat16_rn(v);
            __nv_bfloat16 l = __float2bfloat16_rn(v - __bfloat162float(h));
            int kstep = k >> 4, kk = k & 15;
            int t = (kk & 7) >> 1;
            int idx4 = (kk < 8) ? (kk & 1) : (2 + (kk & 1));
            int ui = ((n >> 3) * 8 + kstep) * 32 + (n & 7) * 4 + t;
            ((__nv_bfloat16*)g_whl)[ui * 8 + idx4]     = h;
            ((__nv_bfloat16*)g_whl)[ui * 8 + 4 + idx4] = l;
        }
    }
}

// ---------------- decode + degree scatter ----------------
__global__ void k_decode_deg(const int* __restrict__ w) {
    int i = blockIdx.x * blockDim.x + threadIdx.x;
    if (i >= N_EDGES) return;
    int s, d;
    if (g_or == 0u) { s = w[2 * i]; d = w[2 * (N_EDGES + i)]; }
    else            { s = w[i];     d = w[N_EDGES + i]; }
    s = min(max(s, 0), N_NODES - 1);
    d = min(max(d, 0), N_NODES - 1);
    g_src[i] = s;
    g_dst[i] = d;
    atomicAdd(&g_deg[d], 1.0f);
}

// -------- init: aggx = x * dinv^2 (self-loop term; replaces zero pass) ----
__global__ void k_init_aggx(const float4* __restrict__ x4) {
    int t = blockIdx.x * blockDim.x + threadIdx.x;  // N*32 threads
    if (t < N_NODES * 32) {
        int node = t >> 5;
        float di = rsqrtf(g_deg[node]);
        float s = di * di;
        float4 v = x4[t];
        v.x *= s; v.y *= s; v.z *= s; v.w *= s;
        ((float4*)g_aggx)[t] = v;
    }
}

// ------- edge scatter: 8 edges/warp, on-the-fly norm, MLP=8+ -------
__global__ void k_edge_scatter(const float4* __restrict__ x4) {
    int t = blockIdx.x * blockDim.x + threadIdx.x;
    int w = t >> 5;                  // warp id = edge octet id
    int e0 = w * 8;
    if (e0 >= N_EDGES) return;       // N_EDGES % 8 == 0
    int lane = t & 31;

    // lanes 0-7: src[e0..e0+7]; lanes 8-15: dst[e0..e0+7]
    int nid = 0;
    if (lane < 16)
        nid = (lane < 8) ? g_src[e0 + lane] : g_dst[e0 + lane - 8];
    float dv = (lane < 16) ? rsqrtf(g_deg[nid]) : 0.0f;

    int s0 = __shfl_sync(0xffffffffu, nid, 0);
    int s1 = __shfl_sync(0xffffffffu, nid, 1);
    int s2 = __shfl_sync(0xffffffffu, nid, 2);
    int s3 = __shfl_sync(0xffffffffu, nid, 3);
    int s4 = __shfl_sync(0xffffffffu, nid, 4);
    int s5 = __shfl_sync(0xffffffffu, nid, 5);
    int s6 = __shfl_sync(0xffffffffu, nid, 6);
    int s7 = __shfl_sync(0xffffffffu, nid, 7);

    float4 v0 = x4[(size_t)s0 * 32 + lane];
    float4 v1 = x4[(size_t)s1 * 32 + lane];
    float4 v2 = x4[(size_t)s2 * 32 + lane];
    float4 v3 = x4[(size_t)s3 * 32 + lane];
    float4 v4 = x4[(size_t)s4 * 32 + lane];
    float4 v5 = x4[(size_t)s5 * 32 + lane];
    float4 v6 = x4[(size_t)s6 * 32 + lane];
    float4 v7 = x4[(size_t)s7 * 32 + lane];

#define NRM(i_) (__shfl_sync(0xffffffffu, dv, i_) * \
                 __shfl_sync(0xffffffffu, dv, 8 + i_))
    float n0 = NRM(0), n1 = NRM(1), n2 = NRM(2), n3 = NRM(3);
    float n4 = NRM(4), n5 = NRM(5), n6 = NRM(6), n7 = NRM(7);
#undef NRM

    int d0 = __shfl_sync(0xffffffffu, nid, 8);
    int d1 = __shfl_sync(0xffffffffu, nid, 9);
    int d2 = __shfl_sync(0xffffffffu, nid, 10);
    int d3 = __shfl_sync(0xffffffffu, nid, 11);
    int d4 = __shfl_sync(0xffffffffu, nid, 12);
    int d5 = __shfl_sync(0xffffffffu, nid, 13);
    int d6 = __shfl_sync(0xffffffffu, nid, 14);
    int d7 = __shfl_sync(0xffffffffu, nid, 15);

#define DO_RED(v_, n_, d_)                                                   \
    do {                                                                     \
        float4 vv = v_;                                                      \
        vv.x *= n_; vv.y *= n_; vv.z *= n_; vv.w *= n_;                      \
        float* p = &g_aggx[(size_t)(d_) * N_FEAT + lane * 4];                \
        asm volatile("red.global.add.v4.f32 [%0], {%1,%2,%3,%4};"            \
                     :: "l"(p), "f"(vv.x), "f"(vv.y), "f"(vv.z), "f"(vv.w)   \
                     : "memory");                                            \
    } while (0)
    DO_RED(v0, n0, d0); DO_RED(v1, n1, d1);
    DO_RED(v2, n2, d2); DO_RED(v3, n3, d3);
    DO_RED(v4, n4, d4); DO_RED(v5, n5, d5);
    DO_RED(v6, n6, d6); DO_RED(v7, n7, d7);
#undef DO_RED
}

// --- GEMM: out = relu(aggx @ W + b); 64-row tiles, 32x32 warp tiles ---
#define MMA_BF16(d, a0, a1, a2, a3, b0, b1)                                 \
    asm volatile(                                                           \
        "mma.sync.aligned.m16n8k16.row.col.f32.bf16.bf16.f32 "              \
        "{%0,%1,%2,%3}, {%4,%5,%6,%7}, {%8,%9}, {%0,%1,%2,%3};"             \
        : "+f"(d[0]), "+f"(d[1]), "+f"(d[2]), "+f"(d[3])                    \
        : "r"(a0), "r"(a1), "r"(a2), "r"(a3), "r"(b0), "r"(b1))

#define LDSM_X4(r0_, r1_, r2_, r3_, addr)                                   \
    asm volatile("ldmatrix.sync.aligned.m8n8.x4.shared.b16 "                \
                 "{%0,%1,%2,%3}, [%4];"                                     \
                 : "=r"(r0_), "=r"(r1_), "=r"(r2_), "=r"(r3_) : "r"(addr))

#define A_STRIDE 136
#define SM_AH  0
#define SM_AL  17408
#define SM_TOTAL (2 * 17408)   // 34,816 B

__global__ void __launch_bounds__(256, 4)
k_gemm_relu(const float* __restrict__ b, float* __restrict__ out) {
    extern __shared__ char sm[];
    __nv_bfloat16* Ah = (__nv_bfloat16*)(sm + SM_AH);  // [64][136]
    __nv_bfloat16* Al = (__nv_bfloat16*)(sm + SM_AL);

    int tid = threadIdx.x;
    int warp = tid >> 5, lane = tid & 31;
    int rg2 = warp & 1, nq = warp >> 1;    // 2 row-groups x 4 N-quarters

    uint32_t arow = rg2 * 32 + (lane & 15);
    uint32_t coff = (lane >> 4) * 8;
    uint32_t ah0a = (uint32_t)__cvta_generic_to_shared(
        &Ah[arow * A_STRIDE + coff]);
    uint32_t ah1a = ah0a + 16 * A_STRIDE * 2;
    uint32_t al0a = (uint32_t)__cvta_generic_to_shared(
        &Al[arow * A_STRIDE + coff]);
    uint32_t al1a = al0a + 16 * A_STRIDE * 2;

    int rowbase = blockIdx.x * TILE_M;
    const float4* A4 = (const float4*)g_aggx;

    // ---- stage A tile: aggx -> bf16 hi/lo, packed STS.64 ----
#pragma unroll
    for (int i = 0; i < 8; i++) {             // 64 rows x 32 float4
        int idx = tid + i * 256;
        int r   = idx >> 5;
        int c   = idx & 31;
        int grow = min(rowbase + r, N_NODES - 1);
        float4 va = A4[(size_t)grow * 32 + c];

        __nv_bfloat16 h0 = __float2bfloat16_rn(va.x);
        __nv_bfloat16 h1 = __float2bfloat16_rn(va.y);
        __nv_bfloat16 h2 = __float2bfloat16_rn(va.z);
        __nv_bfloat16 h3 = __float2bfloat16_rn(va.w);
        __nv_bfloat16 l0 = __float2bfloat16_rn(va.x - __bfloat162float(h0));
        __nv_bfloat16 l1 = __float2bfloat16_rn(va.y - __bfloat162float(h1));
        __nv_bfloat16 l2 = __float2bfloat16_rn(va.z - __bfloat162float(h2));
        __nv_bfloat16 l3 = __float2bfloat16_rn(va.w - __bfloat162float(h3));

        uint32_t hu0 = ((uint32_t)*(uint16_t*)&h1 << 16) | *(uint16_t*)&h0;
        uint32_t hu1 = ((uint32_t)*(uint16_t*)&h3 << 16) | *(uint16_t*)&h2;
        uint32_t lu0 = ((uint32_t)*(uint16_t*)&l1 << 16) | *(uint16_t*)&l0;
        uint32_t lu1 = ((uint32_t)*(uint16_t*)&l3 << 16) | *(uint16_t*)&l2;

        *(uint2*)&Ah[r * A_STRIDE + c * 4] = make_uint2(hu0, hu1);
        *(uint2*)&Al[r * A_STRIDE + c * 4] = make_uint2(lu0, lu1);
    }
    __syncthreads();

    // ---- MMA: each warp 32 rows x 32 cols; 6 MMAs per B load ----
    float acc0[4][4], acc1[4][4];
#pragma unroll
    for (int nt = 0; nt < 4; nt++)
#pragma unroll
        for (int j = 0; j < 4; j++) { acc0[nt][j] = 0.0f; acc1[nt][j] = 0.0f; }

#pragma unroll
    for (int ks = 0; ks < 8; ks++) {
        uint32_t a00, a01, a02, a03, a10, a11, a12, a13;
        uint32_t c00, c01, c02, c03, c10, c11, c12, c13;
        LDSM_X4(a00, a01, a02, a03, ah0a + ks * 32);
        LDSM_X4(a10, a11, a12, a13, ah1a + ks * 32);
        LDSM_X4(c00, c01, c02, c03, al0a + ks * 32);
        LDSM_X4(c10, c11, c12, c13, al1a + ks * 32);
#pragma unroll
        for (int nt = 0; nt < 4; nt++) {
            uint4 wv = g_whl[((nq * 4 + nt) * 8 + ks) * 32 + lane];
            MMA_BF16(acc0[nt], a00, a01, a02, a03, wv.x, wv.y);  // ah*bh
            MMA_BF16(acc0[nt], a00, a01, a02, a03, wv.z, wv.w);  // ah*bl
            MMA_BF16(acc0[nt], c00, c01, c02, c03, wv.x, wv.y);  // al*bh
            MMA_BF16(acc1[nt], a10, a11, a12, a13, wv.x, wv.y);
            MMA_BF16(acc1[nt], a10, a11, a12, a13, wv.z, wv.w);
            MMA_BF16(acc1[nt], c10, c11, c12, c13, wv.x, wv.y);
        }
    }

    // ---- epilogue: bias + relu, guarded stores ----
    int g = lane >> 2, t = lane & 3;
#pragma unroll
    for (int mf = 0; mf < 2; mf++) {
        int growA = rowbase + rg2 * 32 + mf * 16 + g;
#pragma unroll
        for (int nt = 0; nt < 4; nt++) {
            float* acc = mf ? acc1[nt] : acc0[nt];
            int c = nq * 32 + nt * 8 + 2 * t;
            float2 bb = *(const float2*)&b[c];
            if (growA < N_NODES) {
                float2 o;
                o.x = fmaxf(acc[0] + bb.x, 0.0f);
                o.y = fmaxf(acc[1] + bb.y, 0.0f);
                *(float2*)&out[(size_t)growA * 128 + c] = o;
            }
            int grow1 = growA + 8;
            if (grow1 < N_NODES) {
                float2 o;
                o.x = fmaxf(acc[2] + bb.x, 0.0f);
                o.y = fmaxf(acc[3] + bb.y, 0.0f);
                *(float2*)&out[(size_t)grow1 * 128 + c] = o;
            }
        }
    }
}

extern "C" void kernel_launch(void* const* d_in, const int* in_sizes, int n_in,
                              void* d_out, int out_size) {
    const float* x  = nullptr;
    const float* W  = nullptr;
    const float* b  = nullptr;
    const void*  ei = nullptr;
    for (int i = 0; i < n_in; i++) {
        switch (in_sizes[i]) {
            case 12800000: x  = (const float*)d_in[i]; break;
            case 16384:    W  = (const float*)d_in[i]; break;
            case 128:      b  = (const float*)d_in[i]; break;
            case 1200000:  ei = d_in[i];               break;
            default: break;
        }
    }
    float* out = (float*)d_out;
    (void)out_size;
    if (!x || !W || !b || !ei) return;

    // 0: deg init + W split + dtype detect
    k_prep<<<DEG_BLKS + WSP_BLKS, 256>>>(W, (const unsigned int*)ei);
    // 1: decode + degree
    k_decode_deg<<<(N_EDGES + 255) / 256, 256>>>((const int*)ei);
    // 2: aggx = x * dinv^2 (self-loop; replaces zero pass)
    {
        long long total = (long long)N_NODES * 32;
        k_init_aggx<<<(int)((total + 255) / 256), 256>>>((const float4*)x);
    }
    // 3: edge scatter (8 edges/warp) — ncu samples this index
    {
        long long total = (long long)(N_EDGES / 8) * 32;
        k_edge_scatter<<<(int)((total + 255) / 256), 256>>>((const float4*)x);
    }
    // 4: GEMM + bias + relu (reads aggx only)
    cudaFuncSetAttribute(k_gemm_relu,
                         cudaFuncAttributeMaxDynamicSharedMemorySize, SM_TOTAL);
    k_gemm_relu<<<NTILES, 256, SM_TOTAL>>>(b, out);
}

// round 15
// speedup vs baseline: 1.0375x; 1.0375x over previous
#include <cuda_runtime.h>
#include <cuda_bf16.h>
#include <cstdint>

#define N_NODES 100000
#define N_EDGES 600000
#define N_FEAT  128
#define TILE_M  64
#define NTILES  ((N_NODES + TILE_M - 1) / TILE_M)   // 1563

// Scratch (device globals). 16B alignment load-bearing for red.v4/int4 loads.
__device__ __align__(16) float g_deg[N_NODES];           // edge count (no self-loop)
__device__ __align__(16) float g_aggx[(size_t)N_NODES * N_FEAT];
__device__ __align__(16) int g_src[N_EDGES];
__device__ __align__(16) int g_dst[N_EDGES];
__device__ unsigned int g_or;   // dtype detection (0 => int64 layout)
// W fragments, hi/lo interleaved: uint4 = {bh.x, bh.y, bl.x, bl.y}
// index = (nb*8 + kstep)*32 + g*4 + t  -> warp load = 512 B contiguous.
__device__ __align__(16) uint4 g_whl[128 * 8 * 4];

// ---- prep: W split + dtype detect (65 blocks; deg/aggx zeroed by memset) ----
#define WSP_BLKS  ((128 * 128 + 255) / 256)       // 64

__global__ void k_prep(const float* __restrict__ W,
                       const unsigned int* __restrict__ ew) {
    int bid = blockIdx.x, tid = threadIdx.x;
    if (bid == WSP_BLKS) {
        // dtype detect: sample 4096 odd words across the buffer
        __shared__ unsigned int s_or;
        if (tid == 0) s_or = 0u;
        __syncthreads();
        unsigned int v = 0u;
#pragma unroll
        for (int k = 0; k < 16; k++) {
            int e = (tid * 16 + k) * 146;      // <= 597,870 < N_EDGES
            v |= ew[2 * e + 1];
        }
#pragma unroll
        for (int s = 16; s > 0; s >>= 1)
            v |= __shfl_xor_sync(0xffffffffu, v, s);
        if ((tid & 31) == 0 && v) atomicOr(&s_or, v);
        __syncthreads();
        if (tid == 0) g_or = s_or;
        return;
    }
    int i = bid * 256 + tid;                   // W split
    if (i < 128 * 128) {
        int k = i >> 7, n = i & 127;
        float v = W[i];
        __nv_bfloat16 h = __float2bfloat16_rn(v);
        __nv_bfloat16 l = __float2bfloat16_rn(v - __bfloat162float(h));
        int kstep = k >> 4, kk = k & 15;
        int t = (kk & 7) >> 1;
        int idx4 = (kk < 8) ? (kk & 1) : (2 + (kk & 1));
        int ui = ((n >> 3) * 8 + kstep) * 32 + (n & 7) * 4 + t;
        ((__nv_bfloat16*)g_whl)[ui * 8 + idx4]     = h;
        ((__nv_bfloat16*)g_whl)[ui * 8 + 4 + idx4] = l;
    }
}

// ---------------- decode + degree scatter (deg pre-zeroed) ----------------
__global__ void k_decode_deg(const int* __restrict__ w) {
    int i = blockIdx.x * blockDim.x + threadIdx.x;
    if (i >= N_EDGES) return;
    int s, d;
    if (g_or == 0u) { s = w[2 * i]; d = w[2 * (N_EDGES + i)]; }
    else            { s = w[i];     d = w[N_EDGES + i]; }
    s = min(max(s, 0), N_NODES - 1);
    d = min(max(d, 0), N_NODES - 1);
    g_src[i] = s;
    g_dst[i] = d;
    atomicAdd(&g_deg[d], 1.0f);
}

// ------- edge scatter: 8 edges/warp, on-the-fly norm (deg+1), MLP=8+ -------
__global__ void k_edge_scatter(const float4* __restrict__ x4) {
    int t = blockIdx.x * blockDim.x + threadIdx.x;
    int w = t >> 5;                  // warp id = edge octet id
    int e0 = w * 8;
    if (e0 >= N_EDGES) return;       // N_EDGES % 8 == 0
    int lane = t & 31;

    // lanes 0-7: src[e0..e0+7]; lanes 8-15: dst[e0..e0+7]
    int nid = 0;
    if (lane < 16)
        nid = (lane < 8) ? g_src[e0 + lane] : g_dst[e0 + lane - 8];
    float dv = (lane < 16) ? rsqrtf(g_deg[nid] + 1.0f) : 0.0f;

    int s0 = __shfl_sync(0xffffffffu, nid, 0);
    int s1 = __shfl_sync(0xffffffffu, nid, 1);
    int s2 = __shfl_sync(0xffffffffu, nid, 2);
    int s3 = __shfl_sync(0xffffffffu, nid, 3);
    int s4 = __shfl_sync(0xffffffffu, nid, 4);
    int s5 = __shfl_sync(0xffffffffu, nid, 5);
    int s6 = __shfl_sync(0xffffffffu, nid, 6);
    int s7 = __shfl_sync(0xffffffffu, nid, 7);

    float4 v0 = x4[(size_t)s0 * 32 + lane];
    float4 v1 = x4[(size_t)s1 * 32 + lane];
    float4 v2 = x4[(size_t)s2 * 32 + lane];
    float4 v3 = x4[(size_t)s3 * 32 + lane];
    float4 v4 = x4[(size_t)s4 * 32 + lane];
    float4 v5 = x4[(size_t)s5 * 32 + lane];
    float4 v6 = x4[(size_t)s6 * 32 + lane];
    float4 v7 = x4[(size_t)s7 * 32 + lane];

#define NRM(i_) (__shfl_sync(0xffffffffu, dv, i_) * \
                 __shfl_sync(0xffffffffu, dv, 8 + i_))
    float n0 = NRM(0), n1 = NRM(1), n2 = NRM(2), n3 = NRM(3);
    float n4 = NRM(4), n5 = NRM(5), n6 = NRM(6), n7 = NRM(7);
#undef NRM

    int d0 = __shfl_sync(0xffffffffu, nid, 8);
    int d1 = __shfl_sync(0xffffffffu, nid, 9);
    int d2 = __shfl_sync(0xffffffffu, nid, 10);
    int d3 = __shfl_sync(0xffffffffu, nid, 11);
    int d4 = __shfl_sync(0xffffffffu, nid, 12);
    int d5 = __shfl_sync(0xffffffffu, nid, 13);
    int d6 = __shfl_sync(0xffffffffu, nid, 14);
    int d7 = __shfl_sync(0xffffffffu, nid, 15);

#define DO_RED(v_, n_, d_)                                                   \
    do {                                                                     \
        float4 vv = v_;                                                      \
        vv.x *= n_; vv.y *= n_; vv.z *= n_; vv.w *= n_;                      \
        float* p = &g_aggx[(size_t)(d_) * N_FEAT + lane * 4];                \
        asm volatile("red.global.add.v4.f32 [%0], {%1,%2,%3,%4};"            \
                     :: "l"(p), "f"(vv.x), "f"(vv.y), "f"(vv.z), "f"(vv.w)   \
                     : "memory");                                            \
    } while (0)
    DO_RED(v0, n0, d0); DO_RED(v1, n1, d1);
    DO_RED(v2, n2, d2); DO_RED(v3, n3, d3);
    DO_RED(v4, n4, d4); DO_RED(v5, n5, d5);
    DO_RED(v6, n6, d6); DO_RED(v7, n7, d7);
#undef DO_RED
}

// --- GEMM: 64-row tiles, 32x32 warp tiles, interleaved W, bf16x3 mma ---
#define MMA_BF16(d, a0, a1, a2, a3, b0, b1)                                 \
    asm volatile(                                                           \
        "mma.sync.aligned.m16n8k16.row.col.f32.bf16.bf16.f32 "              \
        "{%0,%1,%2,%3}, {%4,%5,%6,%7}, {%8,%9}, {%0,%1,%2,%3};"             \
        : "+f"(d[0]), "+f"(d[1]), "+f"(d[2]), "+f"(d[3])                    \
        : "r"(a0), "r"(a1), "r"(a2), "r"(a3), "r"(b0), "r"(b1))

#define LDSM_X4(r0_, r1_, r2_, r3_, addr)                                   \
    asm volatile("ldmatrix.sync.aligned.m8n8.x4.shared.b16 "                \
                 "{%0,%1,%2,%3}, [%4];"                                     \
                 : "=r"(r0_), "=r"(r1_), "=r"(r2_), "=r"(r3_) : "r"(addr))

#define A_STRIDE 136
#define SM_AH  0
#define SM_AL  17408
#define SM_TOTAL (2 * 17408)   // 34,816 B

__global__ void __launch_bounds__(256, 3)
k_gemm_relu(const float4* __restrict__ x4, const float* __restrict__ b,
            float* __restrict__ out) {
    extern __shared__ char sm[];
    __nv_bfloat16* Ah = (__nv_bfloat16*)(sm + SM_AH);  // [64][136]
    __nv_bfloat16* Al = (__nv_bfloat16*)(sm + SM_AL);

    int tid = threadIdx.x;
    int warp = tid >> 5, lane = tid & 31;
    int rg2 = warp & 1, nq = warp >> 1;    // 2 row-groups x 4 N-quarters

    uint32_t arow = rg2 * 32 + (lane & 15);
    uint32_t coff = (lane >> 4) * 8;
    uint32_t ah0a = (uint32_t)__cvta_generic_to_shared(
        &Ah[arow * A_STRIDE + coff]);
    uint32_t ah1a = ah0a + 16 * A_STRIDE * 2;
    uint32_t al0a = (uint32_t)__cvta_generic_to_shared(
        &Al[arow * A_STRIDE + coff]);
    uint32_t al1a = al0a + 16 * A_STRIDE * 2;

    int rowbase = blockIdx.x * TILE_M;
    const float4* A4 = (const float4*)g_aggx;

    // ---- stage A tile: (aggx + x/(deg+1)) -> bf16 hi/lo, packed STS.64 ----
#pragma unroll
    for (int i = 0; i < 8; i++) {             // 64 rows x 32 float4
        int idx = tid + i * 256;
        int r   = idx >> 5;
        int c   = idx & 31;
        int grow = min(rowbase + r, N_NODES - 1);
        float di = rsqrtf(g_deg[grow] + 1.0f);
        float s2 = di * di;
        float4 va = A4[(size_t)grow * 32 + c];
        float4 vx = x4[(size_t)grow * 32 + c];
        va.x += vx.x * s2; va.y += vx.y * s2;
        va.z += vx.z * s2; va.w += vx.w * s2;

        __nv_bfloat16 h0 = __float2bfloat16_rn(va.x);
        __nv_bfloat16 h1 = __float2bfloat16_rn(va.y);
        __nv_bfloat16 h2 = __float2bfloat16_rn(va.z);
        __nv_bfloat16 h3 = __float2bfloat16_rn(va.w);
        __nv_bfloat16 l0 = __float2bfloat16_rn(va.x - __bfloat162float(h0));
        __nv_bfloat16 l1 = __float2bfloat16_rn(va.y - __bfloat162float(h1));
        __nv_bfloat16 l2 = __float2bfloat16_rn(va.z - __bfloat162float(h2));
        __nv_bfloat16 l3 = __float2bfloat16_rn(va.w - __bfloat162float(h3));

        uint32_t hu0 = ((uint32_t)*(uint16_t*)&h1 << 16) | *(uint16_t*)&h0;
        uint32_t hu1 = ((uint32_t)*(uint16_t*)&h3 << 16) | *(uint16_t*)&h2;
        uint32_t lu0 = ((uint32_t)*(uint16_t*)&l1 << 16) | *(uint16_t*)&l0;
        uint32_t lu1 = ((uint32_t)*(uint16_t*)&l3 << 16) | *(uint16_t*)&l2;

        *(uint2*)&Ah[r * A_STRIDE + c * 4] = make_uint2(hu0, hu1);
        *(uint2*)&Al[r * A_STRIDE + c * 4] = make_uint2(lu0, lu1);
    }
    __syncthreads();

    // ---- MMA: each warp 32 rows x 32 cols; 6 MMAs per B load ----
    float acc0[4][4], acc1[4][4];
#pragma unroll
    for (int nt = 0; nt < 4; nt++)
#pragma unroll
        for (int j = 0; j < 4; j++) { acc0[nt][j] = 0.0f; acc1[nt][j] = 0.0f; }

#pragma unroll
    for (int ks = 0; ks < 8; ks++) {
        uint32_t a00, a01, a02, a03, a10, a11, a12, a13;
        uint32_t c00, c01, c02, c03, c10, c11, c12, c13;
        LDSM_X4(a00, a01, a02, a03, ah0a + ks * 32);
        LDSM_X4(a10, a11, a12, a13, ah1a + ks * 32);
        LDSM_X4(c00, c01, c02, c03, al0a + ks * 32);
        LDSM_X4(c10, c11, c12, c13, al1a + ks * 32);
#pragma unroll
        for (int nt = 0; nt < 4; nt++) {
            uint4 wv = g_whl[((nq * 4 + nt) * 8 + ks) * 32 + lane];
            MMA_BF16(acc0[nt], a00, a01, a02, a03, wv.x, wv.y);  // ah*bh
            MMA_BF16(acc0[nt], a00, a01, a02, a03, wv.z, wv.w);  // ah*bl
            MMA_BF16(acc0[nt], c00, c01, c02, c03, wv.x, wv.y);  // al*bh
            MMA_BF16(acc1[nt], a10, a11, a12, a13, wv.x, wv.y);
            MMA_BF16(acc1[nt], a10, a11, a12, a13, wv.z, wv.w);
            MMA_BF16(acc1[nt], c10, c11, c12, c13, wv.x, wv.y);
        }
    }

    // ---- epilogue: bias + relu, guarded stores ----
    int g = lane >> 2, t = lane & 3;
#pragma unroll
    for (int mf = 0; mf < 2; mf++) {
        int growA = rowbase + rg2 * 32 + mf * 16 + g;
#pragma unroll
        for (int nt = 0; nt < 4; nt++) {
            float* acc = mf ? acc1[nt] : acc0[nt];
            int c = nq * 32 + nt * 8 + 2 * t;
            float2 bb = *(const float2*)&b[c];
            if (growA < N_NODES) {
                float2 o;
                o.x = fmaxf(acc[0] + bb.x, 0.0f);
                o.y = fmaxf(acc[1] + bb.y, 0.0f);
                *(float2*)&out[(size_t)growA * 128 + c] = o;
            }
            int grow1 = growA + 8;
            if (grow1 < N_NODES) {
                float2 o;
                o.x = fmaxf(acc[2] + bb.x, 0.0f);
                o.y = fmaxf(acc[3] + bb.y, 0.0f);
                *(float2*)&out[(size_t)grow1 * 128 + c] = o;
            }
        }
    }
}

extern "C" void kernel_launch(void* const* d_in, const int* in_sizes, int n_in,
                              void* d_out, int out_size) {
    const float* x  = nullptr;
    const float* W  = nullptr;
    const float* b  = nullptr;
    const void*  ei = nullptr;
    for (int i = 0; i < n_in; i++) {
        switch (in_sizes[i]) {
            case 12800000: x  = (const float*)d_in[i]; break;
            case 16384:    W  = (const float*)d_in[i]; break;
            case 128:      b  = (const float*)d_in[i]; break;
            case 1200000:  ei = d_in[i];               break;
            default: break;
        }
    }
    float* out = (float*)d_out;
    (void)out_size;
    if (!x || !W || !b || !ei) return;

    // memset nodes: zero aggx and deg (graph-capturable, no allocation)
    void* p_aggx = nullptr;
    void* p_deg  = nullptr;
    cudaGetSymbolAddress(&p_aggx, g_aggx);
    cudaGetSymbolAddress(&p_deg,  g_deg);
    cudaMemsetAsync(p_aggx, 0, (size_t)N_NODES * N_FEAT * sizeof(float));
    cudaMemsetAsync(p_deg,  0, (size_t)N_NODES * sizeof(float));

    // W split + dtype detect
    k_prep<<<WSP_BLKS + 1, 256>>>(W, (const unsigned int*)ei);
    // decode + degree
    k_decode_deg<<<(N_EDGES + 255) / 256, 256>>>((const int*)ei);
    // edge scatter (8 edges/warp, fused norm)
    {
        long long total = (long long)(N_EDGES / 8) * 32;
        k_edge_scatter<<<(int)((total + 255) / 256), 256>>>((const float4*)x);
    }
    // GEMM + self-loop + bias + relu
    cudaFuncSetAttribute(k_gemm_relu,
                         cudaFuncAttributeMaxDynamicSharedMemorySize, SM_TOTAL);
    k_gemm_relu<<<NTILES, 256, SM_TOTAL>>>((const float4*)x, b, out);
}

// round 16
// speedup vs baseline: 1.0490x; 1.0111x over previous
#include <cuda_runtime.h>
#include <cuda_bf16.h>
#include <cstdint>

#define N_NODES 100000
#define N_EDGES 600000
#define N_FEAT  128
#define TILE_M  64
#define NTILES  ((N_NODES + TILE_M - 1) / TILE_M)   // 1563

// Scratch (device globals). 16B alignment load-bearing for red.v4/int4 loads.
__device__ __align__(16) float g_deg[N_NODES];
__device__ __align__(16) float g_aggx[(size_t)N_NODES * N_FEAT];
__device__ __align__(16) int g_src[N_EDGES];
__device__ __align__(16) int g_dst[N_EDGES];
__device__ unsigned int g_or;   // dtype detection (0 => int64 layout)
// W fragments, hi/lo interleaved: uint4 = {bh.x, bh.y, bl.x, bl.y}
// index = (nb*8 + kstep)*32 + g*4 + t  -> warp load = 512 B contiguous.
__device__ __align__(16) uint4 g_whl[128 * 8 * 4];

// ---- stream 0: deg init + dtype detect ----
#define DEG_BLKS  ((N_NODES + 255) / 256)         // 391

__global__ void k_init0(const unsigned int* __restrict__ ew) {
    int bid = blockIdx.x, tid = threadIdx.x;
    if (bid < DEG_BLKS) {
        int i = bid * 256 + tid;
        if (i < N_NODES) g_deg[i] = 1.0f;          // self-loop pre-counted
        return;
    }
    // detect block: sample 4096 odd words across the buffer
    __shared__ unsigned int s_or;
    if (tid == 0) s_or = 0u;
    __syncthreads();
    unsigned int v = 0u;
#pragma unroll
    for (int k = 0; k < 16; k++) {
        int e = (tid * 16 + k) * 146;              // <= 597,870 < N_EDGES
        v |= ew[2 * e + 1];
    }
#pragma unroll
    for (int s = 16; s > 0; s >>= 1)
        v |= __shfl_xor_sync(0xffffffffu, v, s);
    if ((tid & 31) == 0 && v) atomicOr(&s_or, v);
    __syncthreads();
    if (tid == 0) g_or = s_or;
}

// ---- side stream: zero aggx + W split ----
#define ZERO_BLKS ((N_NODES * 32 + 255) / 256)    // 12,500
#define WSP_BLKS  ((128 * 128 + 255) / 256)       // 64

__global__ void k_zero_w(const float* __restrict__ W) {
    int bid = blockIdx.x, tid = threadIdx.x;
    if (bid < ZERO_BLKS) {
        int i = bid * 256 + tid;
        if (i < N_NODES * 32)
            ((float4*)g_aggx)[i] = make_float4(0.f, 0.f, 0.f, 0.f);
        return;
    }
    int i = (bid - ZERO_BLKS) * 256 + tid;         // W split
    if (i < 128 * 128) {
        int k = i >> 7, n = i & 127;
        float v = W[i];
        __nv_bfloat16 h = __float2bfloat16_rn(v);
        __nv_bfloat16 l = __float2bfloat16_rn(v - __bfloat162float(h));
        int kstep = k >> 4, kk = k & 15;
        int t = (kk & 7) >> 1;
        int idx4 = (kk < 8) ? (kk & 1) : (2 + (kk & 1));
        int ui = ((n >> 3) * 8 + kstep) * 32 + (n & 7) * 4 + t;
        ((__nv_bfloat16*)g_whl)[ui * 8 + idx4]     = h;
        ((__nv_bfloat16*)g_whl)[ui * 8 + 4 + idx4] = l;
    }
}

// ---------------- decode + degree scatter ----------------
__global__ void k_decode_deg(const int* __restrict__ w) {
    int i = blockIdx.x * blockDim.x + threadIdx.x;
    if (i >= N_EDGES) return;
    int s, d;
    if (g_or == 0u) { s = w[2 * i]; d = w[2 * (N_EDGES + i)]; }
    else            { s = w[i];     d = w[N_EDGES + i]; }
    s = min(max(s, 0), N_NODES - 1);
    d = min(max(d, 0), N_NODES - 1);
    g_src[i] = s;
    g_dst[i] = d;
    atomicAdd(&g_deg[d], 1.0f);
}

// ------- edge scatter: 8 edges/warp, on-the-fly norm, MLP=8+ -------
__global__ void k_edge_scatter(const float4* __restrict__ x4) {
    int t = blockIdx.x * blockDim.x + threadIdx.x;
    int w = t >> 5;                  // warp id = edge octet id
    int e0 = w * 8;
    if (e0 >= N_EDGES) return;       // N_EDGES % 8 == 0
    int lane = t & 31;

    int nid = 0;
    if (lane < 16)
        nid = (lane < 8) ? g_src[e0 + lane] : g_dst[e0 + lane - 8];
    float dv = (lane < 16) ? rsqrtf(g_deg[nid]) : 0.0f;

    int s0 = __shfl_sync(0xffffffffu, nid, 0);
    int s1 = __shfl_sync(0xffffffffu, nid, 1);
    int s2 = __shfl_sync(0xffffffffu, nid, 2);
    int s3 = __shfl_sync(0xffffffffu, nid, 3);
    int s4 = __shfl_sync(0xffffffffu, nid, 4);
    int s5 = __shfl_sync(0xffffffffu, nid, 5);
    int s6 = __shfl_sync(0xffffffffu, nid, 6);
    int s7 = __shfl_sync(0xffffffffu, nid, 7);

    float4 v0 = x4[(size_t)s0 * 32 + lane];
    float4 v1 = x4[(size_t)s1 * 32 + lane];
    float4 v2 = x4[(size_t)s2 * 32 + lane];
    float4 v3 = x4[(size_t)s3 * 32 + lane];
    float4 v4 = x4[(size_t)s4 * 32 + lane];
    float4 v5 = x4[(size_t)s5 * 32 + lane];
    float4 v6 = x4[(size_t)s6 * 32 + lane];
    float4 v7 = x4[(size_t)s7 * 32 + lane];

#define NRM(i_) (__shfl_sync(0xffffffffu, dv, i_) * \
                 __shfl_sync(0xffffffffu, dv, 8 + i_))
    float n0 = NRM(0), n1 = NRM(1), n2 = NRM(2), n3 = NRM(3);
    float n4 = NRM(4), n5 = NRM(5), n6 = NRM(6), n7 = NRM(7);
#undef NRM

    int d0 = __shfl_sync(0xffffffffu, nid, 8);
    int d1 = __shfl_sync(0xffffffffu, nid, 9);
    int d2 = __shfl_sync(0xffffffffu, nid, 10);
    int d3 = __shfl_sync(0xffffffffu, nid, 11);
    int d4 = __shfl_sync(0xffffffffu, nid, 12);
    int d5 = __shfl_sync(0xffffffffu, nid, 13);
    int d6 = __shfl_sync(0xffffffffu, nid, 14);
    int d7 = __shfl_sync(0xffffffffu, nid, 15);

#define DO_RED(v_, n_, d_)                                                   \
    do {                                                                     \
        float4 vv = v_;                                                      \
        vv.x *= n_; vv.y *= n_; vv.z *= n_; vv.w *= n_;                      \
        float* p = &g_aggx[(size_t)(d_) * N_FEAT + lane * 4];                \
        asm volatile("red.global.add.v4.f32 [%0], {%1,%2,%3,%4};"            \
                     :: "l"(p), "f"(vv.x), "f"(vv.y), "f"(vv.z), "f"(vv.w)   \
                     : "memory");                                            \
    } while (0)
    DO_RED(v0, n0, d0); DO_RED(v1, n1, d1);
    DO_RED(v2, n2, d2); DO_RED(v3, n3, d3);
    DO_RED(v4, n4, d4); DO_RED(v5, n5, d5);
    DO_RED(v6, n6, d6); DO_RED(v7, n7, d7);
#undef DO_RED
}

// --- GEMM: 64-row tiles, 32x32 warp tiles, interleaved W, bf16x3 mma ---
#define MMA_BF16(d, a0, a1, a2, a3, b0, b1)                                 \
    asm volatile(                                                           \
        "mma.sync.aligned.m16n8k16.row.col.f32.bf16.bf16.f32 "              \
        "{%0,%1,%2,%3}, {%4,%5,%6,%7}, {%8,%9}, {%0,%1,%2,%3};"             \
        : "+f"(d[0]), "+f"(d[1]), "+f"(d[2]), "+f"(d[3])                    \
        : "r"(a0), "r"(a1), "r"(a2), "r"(a3), "r"(b0), "r"(b1))

#define LDSM_X4(r0_, r1_, r2_, r3_, addr)                                   \
    asm volatile("ldmatrix.sync.aligned.m8n8.x4.shared.b16 "                \
                 "{%0,%1,%2,%3}, [%4];"                                     \
                 : "=r"(r0_), "=r"(r1_), "=r"(r2_), "=r"(r3_) : "r"(addr))

#define A_STRIDE 136
#define SM_AH  0
#define SM_AL  17408
#define SM_TOTAL (2 * 17408)   // 34,816 B

__global__ void __launch_bounds__(256, 3)
k_gemm_relu(const float4* __restrict__ x4, const float* __restrict__ b,
            float* __restrict__ out) {
    extern __shared__ char sm[];
    __nv_bfloat16* Ah = (__nv_bfloat16*)(sm + SM_AH);  // [64][136]
    __nv_bfloat16* Al = (__nv_bfloat16*)(sm + SM_AL);

    int tid = threadIdx.x;
    int warp = tid >> 5, lane = tid & 31;
    int rg2 = warp & 1, nq = warp >> 1;    // 2 row-groups x 4 N-quarters

    uint32_t arow = rg2 * 32 + (lane & 15);
    uint32_t coff = (lane >> 4) * 8;
    uint32_t ah0a = (uint32_t)__cvta_generic_to_shared(
        &Ah[arow * A_STRIDE + coff]);
    uint32_t ah1a = ah0a + 16 * A_STRIDE * 2;
    uint32_t al0a = (uint32_t)__cvta_generic_to_shared(
        &Al[arow * A_STRIDE + coff]);
    uint32_t al1a = al0a + 16 * A_STRIDE * 2;

    int rowbase = blockIdx.x * TILE_M;
    const float4* A4 = (const float4*)g_aggx;

    // ---- stage A tile: (aggx + x*dinv^2) -> bf16 hi/lo, packed STS.64 ----
#pragma unroll
    for (int i = 0; i < 8; i++) {             // 64 rows x 32 float4
        int idx = tid + i * 256;
        int r   = idx >> 5;
        int c   = idx & 31;
        int grow = min(rowbase + r, N_NODES - 1);
        float di = rsqrtf(g_deg[grow]);
        float s2 = di * di;
        float4 va = A4[(size_t)grow * 32 + c];
        float4 vx = x4[(size_t)grow * 32 + c];
        va.x += vx.x * s2; va.y += vx.y * s2;
        va.z += vx.z * s2; va.w += vx.w * s2;

        __nv_bfloat16 h0 = __float2bfloat16_rn(va.x);
        __nv_bfloat16 h1 = __float2bfloat16_rn(va.y);
        __nv_bfloat16 h2 = __float2bfloat16_rn(va.z);
        __nv_bfloat16 h3 = __float2bfloat16_rn(va.w);
        __nv_bfloat16 l0 = __float2bfloat16_rn(va.x - __bfloat162float(h0));
        __nv_bfloat16 l1 = __float2bfloat16_rn(va.y - __bfloat162float(h1));
        __nv_bfloat16 l2 = __float2bfloat16_rn(va.z - __bfloat162float(h2));
        __nv_bfloat16 l3 = __float2bfloat16_rn(va.w - __bfloat162float(h3));

        uint32_t hu0 = ((uint32_t)*(uint16_t*)&h1 << 16) | *(uint16_t*)&h0;
        uint32_t hu1 = ((uint32_t)*(uint16_t*)&h3 << 16) | *(uint16_t*)&h2;
        uint32_t lu0 = ((uint32_t)*(uint16_t*)&l1 << 16) | *(uint16_t*)&l0;
        uint32_t lu1 = ((uint32_t)*(uint16_t*)&l3 << 16) | *(uint16_t*)&l2;

        *(uint2*)&Ah[r * A_STRIDE + c * 4] = make_uint2(hu0, hu1);
        *(uint2*)&Al[r * A_STRIDE + c * 4] = make_uint2(lu0, lu1);
    }
    __syncthreads();

    // ---- MMA: each warp 32 rows x 32 cols; 6 MMAs per B load ----
    float acc0[4][4], acc1[4][4];
#pragma unroll
    for (int nt = 0; nt < 4; nt++)
#pragma unroll
        for (int j = 0; j < 4; j++) { acc0[nt][j] = 0.0f; acc1[nt][j] = 0.0f; }

#pragma unroll
    for (int ks = 0; ks < 8; ks++) {
        uint32_t a00, a01, a02, a03, a10, a11, a12, a13;
        uint32_t c00, c01, c02, c03, c10, c11, c12, c13;
        LDSM_X4(a00, a01, a02, a03, ah0a + ks * 32);
        LDSM_X4(a10, a11, a12, a13, ah1a + ks * 32);
        LDSM_X4(c00, c01, c02, c03, al0a + ks * 32);
        LDSM_X4(c10, c11, c12, c13, al1a + ks * 32);
#pragma unroll
        for (int nt = 0; nt < 4; nt++) {
            uint4 wv = g_whl[((nq * 4 + nt) * 8 + ks) * 32 + lane];
            MMA_BF16(acc0[nt], a00, a01, a02, a03, wv.x, wv.y);  // ah*bh
            MMA_BF16(acc0[nt], a00, a01, a02, a03, wv.z, wv.w);  // ah*bl
            MMA_BF16(acc0[nt], c00, c01, c02, c03, wv.x, wv.y);  // al*bh
            MMA_BF16(acc1[nt], a10, a11, a12, a13, wv.x, wv.y);
            MMA_BF16(acc1[nt], a10, a11, a12, a13, wv.z, wv.w);
            MMA_BF16(acc1[nt], c10, c11, c12, c13, wv.x, wv.y);
        }
    }

    // ---- epilogue: bias + relu, guarded stores ----
    int g = lane >> 2, t = lane & 3;
#pragma unroll
    for (int mf = 0; mf < 2; mf++) {
        int growA = rowbase + rg2 * 32 + mf * 16 + g;
#pragma unroll
        for (int nt = 0; nt < 4; nt++) {
            float* acc = mf ? acc1[nt] : acc0[nt];
            int c = nq * 32 + nt * 8 + 2 * t;
            float2 bb = *(const float2*)&b[c];
            if (growA < N_NODES) {
                float2 o;
                o.x = fmaxf(acc[0] + bb.x, 0.0f);
                o.y = fmaxf(acc[1] + bb.y, 0.0f);
                *(float2*)&out[(size_t)growA * 128 + c] = o;
            }
            int grow1 = growA + 8;
            if (grow1 < N_NODES) {
                float2 o;
                o.x = fmaxf(acc[2] + bb.x, 0.0f);
                o.y = fmaxf(acc[3] + bb.y, 0.0f);
                *(float2*)&out[(size_t)grow1 * 128 + c] = o;
            }
        }
    }
}

extern "C" void kernel_launch(void* const* d_in, const int* in_sizes, int n_in,
                              void* d_out, int out_size) {
    const float* x  = nullptr;
    const float* W  = nullptr;
    const float* b  = nullptr;
    const void*  ei = nullptr;
    for (int i = 0; i < n_in; i++) {
        switch (in_sizes[i]) {
            case 12800000: x  = (const float*)d_in[i]; break;
            case 16384:    W  = (const float*)d_in[i]; break;
            case 128:      b  = (const float*)d_in[i]; break;
            case 1200000:  ei = d_in[i];               break;
            default: break;
        }
    }
    float* out = (float*)d_out;
    (void)out_size;
    if (!x || !W || !b || !ei) return;

    // Fork a side stream so {zero aggx + W split} overlaps
    // {deg init + detect -> decode}. Host-side objects only; the captured
    // graph is identical on every call. (Leaked: ~3 calls total.)
    cudaStream_t sB;
    cudaEvent_t eF, eJ;
    cudaStreamCreateWithFlags(&sB, cudaStreamNonBlocking);
    cudaEventCreateWithFlags(&eF, cudaEventDisableTiming);
    cudaEventCreateWithFlags(&eJ, cudaEventDisableTiming);

    cudaEventRecord(eF, 0);                 // fork at root
    cudaStreamWaitEvent(sB, eF, 0);

    // side stream: zero aggx + W split
    k_zero_w<<<ZERO_BLKS + WSP_BLKS, 256, 0, sB>>>(W);

    // stream 0: deg init + detect, then decode + degree
    k_init0<<<DEG_BLKS + 1, 256>>>((const unsigned int*)ei);
    k_decode_deg<<<(N_EDGES + 255) / 256, 256>>>((const int*)ei);

    cudaEventRecord(eJ, sB);                // join
    cudaStreamWaitEvent(0, eJ, 0);

    // edge scatter (8 edges/warp, fused norm)
    {
        long long total = (long long)(N_EDGES / 8) * 32;
        k_edge_scatter<<<(int)((total + 255) / 256), 256>>>((const float4*)x);
    }
    // GEMM + self-loop + bias + relu
    cudaFuncSetAttribute(k_gemm_relu,
                         cudaFuncAttributeMaxDynamicSharedMemorySize, SM_TOTAL);
    k_gemm_relu<<<NTILES, 256, SM_TOTAL>>>((const float4*)x, b, out);
}

// round 17
// speedup vs baseline: 1.1033x; 1.0518x over previous
#include <cuda_runtime.h>
#include <cuda_bf16.h>
#include <cstdint>

#define N_NODES 100000
#define N_EDGES 600000
#define N_FEAT  128
#define TILE_M  64
#define NTILES  ((N_NODES + TILE_M - 1) / TILE_M)   // 1563

// Scratch (device globals). 16B alignment load-bearing for red.v4 loads.
__device__ __align__(16) float g_deg[N_NODES];
__device__ __align__(16) float g_aggx[(size_t)N_NODES * N_FEAT];
__device__ unsigned int g_or;   // dtype detection (0 => int64 layout)
// W fragments, hi/lo interleaved: uint4 = {bh.x, bh.y, bl.x, bl.y}
// index = (nb*8 + kstep)*32 + g*4 + t  -> warp load = 512 B contiguous.
__device__ __align__(16) uint4 g_whl[128 * 8 * 4];

// ---- prep: zero aggx + deg init + W split + dtype detect (one launch) ----
#define ZERO_BLKS ((N_NODES * 32 + 255) / 256)    // float4 units: 12,500
#define DEG_BLKS  ((N_NODES + 255) / 256)         // 391
#define WSP_BLKS  ((128 * 128 + 255) / 256)       // 64

__global__ void k_prep(const float* __restrict__ W,
                       const unsigned int* __restrict__ ew) {
    int bid = blockIdx.x, tid = threadIdx.x;
    if (bid < ZERO_BLKS) {
        int i = bid * 256 + tid;
        if (i < N_NODES * 32)
            ((float4*)g_aggx)[i] = make_float4(0.f, 0.f, 0.f, 0.f);
        return;
    }
    bid -= ZERO_BLKS;
    if (bid < DEG_BLKS) {
        int i = bid * 256 + tid;
        if (i < N_NODES) g_deg[i] = 1.0f;          // self-loop pre-counted
        if (bid == 0) {
            __shared__ unsigned int s_or;
            if (tid == 0) s_or = 0u;
            __syncthreads();
            unsigned int v = 0u;
#pragma unroll
            for (int k = 0; k < 16; k++) {
                int e = (tid * 16 + k) * 146;      // <= 597,870 < N_EDGES
                v |= ew[2 * e + 1];
            }
#pragma unroll
            for (int s = 16; s > 0; s >>= 1)
                v |= __shfl_xor_sync(0xffffffffu, v, s);
            if ((tid & 31) == 0 && v) atomicOr(&s_or, v);
            __syncthreads();
            if (tid == 0) g_or = s_or;
        }
    } else {
        int i = (bid - DEG_BLKS) * 256 + tid;      // W split
        if (i < 128 * 128) {
            int k = i >> 7, n = i & 127;
            float v = W[i];
            __nv_bfloat16 h = __float2bfloat16_rn(v);
            __nv_bfloat16 l = __float2bfloat16_rn(v - __bfloat162float(h));
            int kstep = k >> 4, kk = k & 15;
            int t = (kk & 7) >> 1;
            int idx4 = (kk < 8) ? (kk & 1) : (2 + (kk & 1));
            int ui = ((n >> 3) * 8 + kstep) * 32 + (n & 7) * 4 + t;
            ((__nv_bfloat16*)g_whl)[ui * 8 + idx4]     = h;
            ((__nv_bfloat16*)g_whl)[ui * 8 + 4 + idx4] = l;
        }
    }
}

// ---------------- degree histogram (dst only, direct from edge_index) -----
__global__ void k_deg(const int* __restrict__ w) {
    int i = blockIdx.x * blockDim.x + threadIdx.x;
    if (i >= N_EDGES) return;
    int d = (g_or == 0u) ? w[2 * (N_EDGES + i)] : w[N_EDGES + i];
    d = min(max(d, 0), N_NODES - 1);
    atomicAdd(&g_deg[d], 1.0f);
}

// -- edge scatter: 8 edges/warp, indices decoded inline, MLP=8+ --
__global__ void k_edge_scatter(const float4* __restrict__ x4,
                               const int* __restrict__ w) {
    int t = blockIdx.x * blockDim.x + threadIdx.x;
    int wp = t >> 5;                 // warp id = edge octet id
    int e0 = wp * 8;
    if (e0 >= N_EDGES) return;       // N_EDGES % 8 == 0
    int lane = t & 31;

    // lanes 0-7: src[e0..e0+7]; lanes 8-15: dst[e0..e0+7], decoded inline
    int nid = 0;
    if (lane < 16) {
        int e = e0 + (lane & 7);
        int pos = (lane < 8) ? e : (N_EDGES + e);
        nid = (g_or == 0u) ? w[2 * pos] : w[pos];
        nid = min(max(nid, 0), N_NODES - 1);
    }
    float dv = (lane < 16) ? rsqrtf(g_deg[nid]) : 0.0f;

    int s0 = __shfl_sync(0xffffffffu, nid, 0);
    int s1 = __shfl_sync(0xffffffffu, nid, 1);
    int s2 = __shfl_sync(0xffffffffu, nid, 2);
    int s3 = __shfl_sync(0xffffffffu, nid, 3);
    int s4 = __shfl_sync(0xffffffffu, nid, 4);
    int s5 = __shfl_sync(0xffffffffu, nid, 5);
    int s6 = __shfl_sync(0xffffffffu, nid, 6);
    int s7 = __shfl_sync(0xffffffffu, nid, 7);

    float4 v0 = x4[(size_t)s0 * 32 + lane];
    float4 v1 = x4[(size_t)s1 * 32 + lane];
    float4 v2 = x4[(size_t)s2 * 32 + lane];
    float4 v3 = x4[(size_t)s3 * 32 + lane];
    float4 v4 = x4[(size_t)s4 * 32 + lane];
    float4 v5 = x4[(size_t)s5 * 32 + lane];
    float4 v6 = x4[(size_t)s6 * 32 + lane];
    float4 v7 = x4[(size_t)s7 * 32 + lane];

#define NRM(i_) (__shfl_sync(0xffffffffu, dv, i_) * \
                 __shfl_sync(0xffffffffu, dv, 8 + i_))
    float n0 = NRM(0), n1 = NRM(1), n2 = NRM(2), n3 = NRM(3);
    float n4 = NRM(4), n5 = NRM(5), n6 = NRM(6), n7 = NRM(7);
#undef NRM

    int d0 = __shfl_sync(0xffffffffu, nid, 8);
    int d1 = __shfl_sync(0xffffffffu, nid, 9);
    int d2 = __shfl_sync(0xffffffffu, nid, 10);
    int d3 = __shfl_sync(0xffffffffu, nid, 11);
    int d4 = __shfl_sync(0xffffffffu, nid, 12);
    int d5 = __shfl_sync(0xffffffffu, nid, 13);
    int d6 = __shfl_sync(0xffffffffu, nid, 14);
    int d7 = __shfl_sync(0xffffffffu, nid, 15);

#define DO_RED(v_, n_, d_)                                                   \
    do {                                                                     \
        float4 vv = v_;                                                      \
        vv.x *= n_; vv.y *= n_; vv.z *= n_; vv.w *= n_;                      \
        float* p = &g_aggx[(size_t)(d_) * N_FEAT + lane * 4];                \
        asm volatile("red.global.add.v4.f32 [%0], {%1,%2,%3,%4};"            \
                     :: "l"(p), "f"(vv.x), "f"(vv.y), "f"(vv.z), "f"(vv.w)   \
                     : "memory");                                            \
    } while (0)
    DO_RED(v0, n0, d0); DO_RED(v1, n1, d1);
    DO_RED(v2, n2, d2); DO_RED(v3, n3, d3);
    DO_RED(v4, n4, d4); DO_RED(v5, n5, d5);
    DO_RED(v6, n6, d6); DO_RED(v7, n7, d7);
#undef DO_RED
}

// --- GEMM: 64-row tiles, 32x32 warp tiles, interleaved W, bf16x3 mma ---
#define MMA_BF16(d, a0, a1, a2, a3, b0, b1)                                 \
    asm volatile(                                                           \
        "mma.sync.aligned.m16n8k16.row.col.f32.bf16.bf16.f32 "              \
        "{%0,%1,%2,%3}, {%4,%5,%6,%7}, {%8,%9}, {%0,%1,%2,%3};"             \
        : "+f"(d[0]), "+f"(d[1]), "+f"(d[2]), "+f"(d[3])                    \
        : "r"(a0), "r"(a1), "r"(a2), "r"(a3), "r"(b0), "r"(b1))

#define LDSM_X4(r0_, r1_, r2_, r3_, addr)                                   \
    asm volatile("ldmatrix.sync.aligned.m8n8.x4.shared.b16 "                \
                 "{%0,%1,%2,%3}, [%4];"                                     \
                 : "=r"(r0_), "=r"(r1_), "=r"(r2_), "=r"(r3_) : "r"(addr))

#define A_STRIDE 136
#define SM_AH  0
#define SM_AL  17408
#define SM_TOTAL (2 * 17408)   // 34,816 B

__global__ void __launch_bounds__(256, 3)
k_gemm_relu(const float4* __restrict__ x4, const float* __restrict__ b,
            float* __restrict__ out) {
    extern __shared__ char sm[];
    __nv_bfloat16* Ah = (__nv_bfloat16*)(sm + SM_AH);  // [64][136]
    __nv_bfloat16* Al = (__nv_bfloat16*)(sm + SM_AL);

    int tid = threadIdx.x;
    int warp = tid >> 5, lane = tid & 31;
    int rg2 = warp & 1, nq = warp >> 1;    // 2 row-groups x 4 N-quarters

    uint32_t arow = rg2 * 32 + (lane & 15);
    uint32_t coff = (lane >> 4) * 8;
    uint32_t ah0a = (uint32_t)__cvta_generic_to_shared(
        &Ah[arow * A_STRIDE + coff]);
    uint32_t ah1a = ah0a + 16 * A_STRIDE * 2;
    uint32_t al0a = (uint32_t)__cvta_generic_to_shared(
        &Al[arow * A_STRIDE + coff]);
    uint32_t al1a = al0a + 16 * A_STRIDE * 2;

    int rowbase = blockIdx.x * TILE_M;
    const float4* A4 = (const float4*)g_aggx;

    // ---- stage A tile: (aggx + x*dinv^2) -> bf16 hi/lo, packed STS.64 ----
#pragma unroll
    for (int i = 0; i < 8; i++) {             // 64 rows x 32 float4
        int idx = tid + i * 256;
        int r   = idx >> 5;
        int c   = idx & 31;
        int grow = min(rowbase + r, N_NODES - 1);
        float di = rsqrtf(g_deg[grow]);
        float s2 = di * di;
        float4 va = A4[(size_t)grow * 32 + c];
        float4 vx = x4[(size_t)grow * 32 + c];
        va.x += vx.x * s2; va.y += vx.y * s2;
        va.z += vx.z * s2; va.w += vx.w * s2;

        __nv_bfloat16 h0 = __float2bfloat16_rn(va.x);
        __nv_bfloat16 h1 = __float2bfloat16_rn(va.y);
        __nv_bfloat16 h2 = __float2bfloat16_rn(va.z);
        __nv_bfloat16 h3 = __float2bfloat16_rn(va.w);
        __nv_bfloat16 l0 = __float2bfloat16_rn(va.x - __bfloat162float(h0));
        __nv_bfloat16 l1 = __float2bfloat16_rn(va.y - __bfloat162float(h1));
        __nv_bfloat16 l2 = __float2bfloat16_rn(va.z - __bfloat162float(h2));
        __nv_bfloat16 l3 = __float2bfloat16_rn(va.w - __bfloat162float(h3));

        uint32_t hu0 = ((uint32_t)*(uint16_t*)&h1 << 16) | *(uint16_t*)&h0;
        uint32_t hu1 = ((uint32_t)*(uint16_t*)&h3 << 16) | *(uint16_t*)&h2;
        uint32_t lu0 = ((uint32_t)*(uint16_t*)&l1 << 16) | *(uint16_t*)&l0;
        uint32_t lu1 = ((uint32_t)*(uint16_t*)&l3 << 16) | *(uint16_t*)&l2;

        *(uint2*)&Ah[r * A_STRIDE + c * 4] = make_uint2(hu0, hu1);
        *(uint2*)&Al[r * A_STRIDE + c * 4] = make_uint2(lu0, lu1);
    }
    __syncthreads();

    // ---- MMA: each warp 32 rows x 32 cols; 6 MMAs per B load ----
    float acc0[4][4], acc1[4][4];
#pragma unroll
    for (int nt = 0; nt < 4; nt++)
#pragma unroll
        for (int j = 0; j < 4; j++) { acc0[nt][j] = 0.0f; acc1[nt][j] = 0.0f; }

#pragma unroll
    for (int ks = 0; ks < 8; ks++) {
        uint32_t a00, a01, a02, a03, a10, a11, a12, a13;
        uint32_t c00, c01, c02, c03, c10, c11, c12, c13;
        LDSM_X4(a00, a01, a02, a03, ah0a + ks * 32);
        LDSM_X4(a10, a11, a12, a13, ah1a + ks * 32);
        LDSM_X4(c00, c01, c02, c03, al0a + ks * 32);
        LDSM_X4(c10, c11, c12, c13, al1a + ks * 32);
#pragma unroll
        for (int nt = 0; nt < 4; nt++) {
            uint4 wv = g_whl[((nq * 4 + nt) * 8 + ks) * 32 + lane];
            MMA_BF16(acc0[nt], a00, a01, a02, a03, wv.x, wv.y);  // ah*bh
            MMA_BF16(acc0[nt], a00, a01, a02, a03, wv.z, wv.w);  // ah*bl
            MMA_BF16(acc0[nt], c00, c01, c02, c03, wv.x, wv.y);  // al*bh
            MMA_BF16(acc1[nt], a10, a11, a12, a13, wv.x, wv.y);
            MMA_BF16(acc1[nt], a10, a11, a12, a13, wv.z, wv.w);
            MMA_BF16(acc1[nt], c10, c11, c12, c13, wv.x, wv.y);
        }
    }

    // ---- epilogue: bias + relu, guarded stores ----
    int g = lane >> 2, t = lane & 3;
#pragma unroll
    for (int mf = 0; mf < 2; mf++) {
        int growA = rowbase + rg2 * 32 + mf * 16 + g;
#pragma unroll
        for (int nt = 0; nt < 4; nt++) {
            float* acc = mf ? acc1[nt] : acc0[nt];
            int c = nq * 32 + nt * 8 + 2 * t;
            float2 bb = *(const float2*)&b[c];
            if (growA < N_NODES) {
                float2 o;
                o.x = fmaxf(acc[0] + bb.x, 0.0f);
                o.y = fmaxf(acc[1] + bb.y, 0.0f);
                *(float2*)&out[(size_t)growA * 128 + c] = o;
            }
            int grow1 = growA + 8;
            if (grow1 < N_NODES) {
                float2 o;
                o.x = fmaxf(acc[2] + bb.x, 0.0f);
                o.y = fmaxf(acc[3] + bb.y, 0.0f);
                *(float2*)&out[(size_t)grow1 * 128 + c] = o;
            }
        }
    }
}

extern "C" void kernel_launch(void* const* d_in, const int* in_sizes, int n_in,
                              void* d_out, int out_size) {
    const float* x  = nullptr;
    const float* W  = nullptr;
    const float* b  = nullptr;
    const void*  ei = nullptr;
    for (int i = 0; i < n_in; i++) {
        switch (in_sizes[i]) {
            case 12800000: x  = (const float*)d_in[i]; break;
            case 16384:    W  = (const float*)d_in[i]; break;
            case 128:      b  = (const float*)d_in[i]; break;
            case 1200000:  ei = d_in[i];               break;
            default: break;
        }
    }
    float* out = (float*)d_out;
    (void)out_size;
    if (!x || !W || !b || !ei) return;

    // 0: zero aggx + deg init + W split + dtype detect
    k_prep<<<ZERO_BLKS + DEG_BLKS + WSP_BLKS, 256>>>(W, (const unsigned int*)ei);
    // 1: degree histogram (direct from edge_index)
    k_deg<<<(N_EDGES + 255) / 256, 256>>>((const int*)ei);
    // 2: edge scatter (8 edges/warp, inline decode + norm)
    {
        long long total = (long long)(N_EDGES / 8) * 32;
        k_edge_scatter<<<(int)((total + 255) / 256), 256>>>((const float4*)x,
                                                            (const int*)ei);
    }
    // 3: GEMM + self-loop + bias + relu  (ncu samples index 3)
    cudaFuncSetAttribute(k_gemm_relu,
                         cudaFuncAttributeMaxDynamicSharedMemorySize, SM_TOTAL);
    k_gemm_relu<<<NTILES, 256, SM_TOTAL>>>((const float4*)x, b, out);
}